// round 2
// baseline (speedup 1.0000x reference)
#include <cuda_runtime.h>
#include <cstdint>
#include <math.h>

#define T_TOK 1024
#define H_DIM 2048
#define E_NUM 64
#define I_DIM 512
#define IS_DIM 1024
#define TOPK 8
#define CAP 256

// ---------------- scratch (static device globals; no allocs) ----------------
__device__ int   d_topk_idx[T_TOK * TOPK];
__device__ float d_topk_w[T_TOK * TOPK];
__device__ float d_sgate[T_TOK];
__device__ int   d_cnt[E_NUM];
__device__ int   d_toklist[E_NUM * CAP];
__device__ int   d_pos[T_TOK * TOPK];
__device__ float d_gbuf[(size_t)E_NUM * CAP * I_DIM];   // 33.5 MB
__device__ float d_yb[(size_t)E_NUM * CAP * H_DIM];     // 134 MB
__device__ float d_s1[(size_t)T_TOK * IS_DIM];          // 4 MB
__device__ float d_s2[(size_t)T_TOK * H_DIM];           // 8 MB

// ---------------- helpers ----------------
__device__ __forceinline__ unsigned tf32r(float x) {
    unsigned r;
    asm("cvt.rna.tf32.f32 %0, %1;" : "=r"(r) : "f"(x));
    return r;
}

__device__ __forceinline__ void mma8(float* c, unsigned a0, unsigned a1, unsigned a2,
                                     unsigned a3, unsigned b0, unsigned b1) {
    asm volatile(
        "mma.sync.aligned.m16n8k8.row.col.f32.tf32.tf32.f32 "
        "{%0,%1,%2,%3}, {%4,%5,%6,%7}, {%8,%9}, {%0,%1,%2,%3};"
        : "+f"(c[0]), "+f"(c[1]), "+f"(c[2]), "+f"(c[3])
        : "r"(a0), "r"(a1), "r"(a2), "r"(a3), "r"(b0), "r"(b1));
}

__device__ __forceinline__ void cp16(void* smem_dst, const void* gsrc) {
    unsigned d = (unsigned)__cvta_generic_to_shared(smem_dst);
    asm volatile("cp.async.ca.shared.global [%0], [%1], 16;" :: "r"(d), "l"(gsrc));
}
__device__ __forceinline__ void cp_commit() { asm volatile("cp.async.commit_group;"); }
__device__ __forceinline__ void cp_wait1()  { asm volatile("cp.async.wait_group 1;"); }

// ---------------- router: logits, top-8, softmax, shared gate ----------------
__global__ void router_kernel(const float* __restrict__ x,
                              const float* __restrict__ gw,
                              const float* __restrict__ wsg) {
    int t = blockIdx.x;
    __shared__ float xs[H_DIM];
    __shared__ float logits[E_NUM + 1];
    const float4* xr = (const float4*)(x + (size_t)t * H_DIM);
    for (int i = threadIdx.x; i < H_DIM / 4; i += blockDim.x)
        ((float4*)xs)[i] = xr[i];
    __syncthreads();
    int warp = threadIdx.x >> 5, lane = threadIdx.x & 31;
    for (int u = warp; u < E_NUM + 1; u += 8) {
        const float4* wrow = (const float4*)((u < E_NUM) ? (gw + (size_t)u * H_DIM) : wsg);
        float s = 0.f;
        for (int i = lane; i < H_DIM / 4; i += 32) {
            float4 a = ((const float4*)xs)[i];
            float4 b = wrow[i];
            s += a.x * b.x + a.y * b.y + a.z * b.z + a.w * b.w;
        }
        #pragma unroll
        for (int o = 16; o; o >>= 1) s += __shfl_xor_sync(0xffffffffu, s, o);
        if (lane == 0) logits[u] = s;
    }
    __syncthreads();
    if (threadIdx.x == 0) {
        unsigned long long used = 0ull;
        float vals[TOPK]; int idx[TOPK];
        for (int k = 0; k < TOPK; k++) {
            float best = -INFINITY; int bi = 0;
            for (int e = 0; e < E_NUM; e++)
                if (!((used >> e) & 1ull) && logits[e] > best) { best = logits[e]; bi = e; }
            used |= 1ull << bi; vals[k] = best; idx[k] = bi;
        }
        float m = vals[0], sum = 0.f, w[TOPK];
        for (int k = 0; k < TOPK; k++) { w[k] = expf(vals[k] - m); sum += w[k]; }
        float inv = 1.f / sum;
        for (int k = 0; k < TOPK; k++) {
            d_topk_w[t * TOPK + k]  = w[k] * inv;
            d_topk_idx[t * TOPK + k] = idx[k];
        }
        d_sgate[t] = logits[E_NUM];
    }
}

// ------- dispatch: stable rank within expert over flat (token,slot) order -------
__global__ void dispatch_kernel() {
    int e = blockIdx.x;
    __shared__ int warp_sums[8];
    __shared__ int base_s;
    if (threadIdx.x == 0) base_s = 0;
    int lane = threadIdx.x & 31, warp = threadIdx.x >> 5;
    for (int c = 0; c < T_TOK * TOPK; c += 256) {
        __syncthreads();
        int i = c + threadIdx.x;
        bool m = (d_topk_idx[i] == e);
        unsigned mask = __ballot_sync(0xffffffffu, m);
        if (lane == 0) warp_sums[warp] = __popc(mask);
        __syncthreads();
        int off = 0, total = 0;
        #pragma unroll
        for (int w = 0; w < 8; w++) { int v = warp_sums[w]; total += v; if (w < warp) off += v; }
        if (m) {
            int pos = base_s + off + __popc(mask & ((1u << lane) - 1u));
            d_pos[i] = pos;
            if (pos < CAP) d_toklist[e * CAP + pos] = i >> 3;
        }
        __syncthreads();
        if (threadIdx.x == 0) base_s += total;
    }
    __syncthreads();
    if (threadIdx.x == 0) d_cnt[e] = min(base_s, CAP);
}

// ---------------- dual GEMM (C1=A@B1, C3=A@B3) + SwiGLU epilogue ----------------
#define BM 128
#define BKx 32
#define ASTR 36
#define BSTR_D 72
#define SMEM_DUAL ((2 * BM * ASTR + 2 * 2 * BKx * BSTR_D) * 4)

__global__ void __launch_bounds__(128)
dual_gemm_silu(const float* __restrict__ A, int lda, size_t strideA,
               const int* __restrict__ gather, const int* __restrict__ cnt,
               int mfull, int mtiles,
               const float* __restrict__ B1g, const float* __restrict__ B3g,
               int ldb, size_t strideB,
               float* __restrict__ Out, int ldo, size_t strideOut, int K) {
    extern __shared__ float sm[];
    float* As  = sm;                       // 2 * 128 * 36
    float* B1s = sm + 2 * BM * ASTR;       // 2 * 32 * 72
    float* B3s = B1s + 2 * BKx * BSTR_D;   // 2 * 32 * 72

    int e = blockIdx.x / mtiles;
    int mt = blockIdx.x - e * mtiles;
    int noff = blockIdx.y * 64;
    int nrows = cnt ? (cnt[e] - mt * BM) : (mfull - mt * BM);
    if (nrows <= 0) return;
    int valid = min(BM, nrows);

    int tid = threadIdx.x;
    int acol = (tid & 7) * 4;
    int arow0 = tid >> 3;
    const float* aptr[8];
    #pragma unroll
    for (int i = 0; i < 8; i++) {
        int r = arow0 + i * 16;
        int rr = min(r, valid - 1);
        long grow = gather ? (long)gather[e * CAP + mt * BM + rr] : ((long)mt * BM + rr);
        aptr[i] = A + (size_t)e * strideA + (size_t)grow * lda + acol;
    }
    const float* b1ptr[4];
    const float* b3ptr[4];
    {
        const float* B1 = B1g + (size_t)e * strideB + noff;
        const float* B3 = B3g + (size_t)e * strideB + noff;
        #pragma unroll
        for (int i = 0; i < 4; i++) {
            int slot = tid + i * 128;
            int k = slot >> 4;
            int n4 = (slot & 15) * 4;
            b1ptr[i] = B1 + (size_t)k * ldb + n4;
            b3ptr[i] = B3 + (size_t)k * ldb + n4;
        }
    }

    float c1[4][4][4], c3[4][4][4];
    #pragma unroll
    for (int a = 0; a < 4; a++)
        #pragma unroll
        for (int b = 0; b < 4; b++)
            #pragma unroll
            for (int r = 0; r < 4; r++) { c1[a][b][r] = 0.f; c3[a][b][r] = 0.f; }

    int warp = tid >> 5, lane = tid & 31;
    int wm = warp & 1, wn = warp >> 1;
    int g = lane >> 2, t4 = lane & 3;

    auto issue = [&](int s) {
        float* as = As + s * BM * ASTR;
        #pragma unroll
        for (int i = 0; i < 8; i++) {
            int r = arow0 + i * 16;
            cp16(as + r * ASTR + acol, aptr[i]);
            aptr[i] += BKx;
        }
        float* b1s = B1s + s * BKx * BSTR_D;
        float* b3s = B3s + s * BKx * BSTR_D;
        #pragma unroll
        for (int i = 0; i < 4; i++) {
            int slot = tid + i * 128;
            int k = slot >> 4;
            int n4 = (slot & 15) * 4;
            cp16(b1s + k * BSTR_D + n4, b1ptr[i]);
            cp16(b3s + k * BSTR_D + n4, b3ptr[i]);
            b1ptr[i] += (size_t)BKx * ldb;
            b3ptr[i] += (size_t)BKx * ldb;
        }
    };

    issue(0); cp_commit();
    int nk = K / BKx;
    for (int kb = 0; kb < nk; kb++) {
        int s = kb & 1;
        if (kb + 1 < nk) issue(s ^ 1);
        cp_commit();
        cp_wait1();
        __syncthreads();
        const float* as  = As + s * BM * ASTR;
        const float* b1s = B1s + s * BKx * BSTR_D;
        const float* b3s = B3s + s * BKx * BSTR_D;
        #pragma unroll
        for (int kk = 0; kk < 4; kk++) {
            unsigned af[4][4];
            int kc = kk * 8 + t4;
            #pragma unroll
            for (int mf = 0; mf < 4; mf++) {
                int r0 = wm * 64 + mf * 16 + g;
                af[mf][0] = tf32r(as[r0 * ASTR + kc]);
                af[mf][1] = tf32r(as[(r0 + 8) * ASTR + kc]);
                af[mf][2] = tf32r(as[r0 * ASTR + kc + 4]);
                af[mf][3] = tf32r(as[(r0 + 8) * ASTR + kc + 4]);
            }
            unsigned bf1[4][2], bf3[4][2];
            #pragma unroll
            for (int nf = 0; nf < 4; nf++) {
                int nn = wn * 32 + nf * 8 + g;
                bf1[nf][0] = tf32r(b1s[kc * BSTR_D + nn]);
                bf1[nf][1] = tf32r(b1s[(kc + 4) * BSTR_D + nn]);
                bf3[nf][0] = tf32r(b3s[kc * BSTR_D + nn]);
                bf3[nf][1] = tf32r(b3s[(kc + 4) * BSTR_D + nn]);
            }
            #pragma unroll
            for (int mf = 0; mf < 4; mf++)
                #pragma unroll
                for (int nf = 0; nf < 4; nf++) {
                    mma8(c1[mf][nf], af[mf][0], af[mf][1], af[mf][2], af[mf][3], bf1[nf][0], bf1[nf][1]);
                    mma8(c3[mf][nf], af[mf][0], af[mf][1], af[mf][2], af[mf][3], bf3[nf][0], bf3[nf][1]);
                }
        }
        __syncthreads();
    }

    float* outp = Out + (size_t)e * strideOut + (size_t)mt * BM * ldo + noff;
    #pragma unroll
    for (int mf = 0; mf < 4; mf++)
        #pragma unroll
        for (int nf = 0; nf < 4; nf++) {
            int r0 = wm * 64 + mf * 16 + g;
            int cc = wn * 32 + nf * 8 + t4 * 2;
            #pragma unroll
            for (int h = 0; h < 2; h++) {
                int r = r0 + h * 8;
                if (r < valid) {
                    float v1a = c1[mf][nf][h * 2 + 0], v3a = c3[mf][nf][h * 2 + 0];
                    float v1b = c1[mf][nf][h * 2 + 1], v3b = c3[mf][nf][h * 2 + 1];
                    float ga = (v1a / (1.f + expf(-v1a))) * v3a;
                    float gb = (v1b / (1.f + expf(-v1b))) * v3b;
                    *(float2*)(outp + (size_t)r * ldo + cc) = make_float2(ga, gb);
                }
            }
        }
}

// ---------------- single GEMM (C = A @ B) ----------------
#define BSTR_S 136
#define SMEM_SINGLE ((2 * BM * ASTR + 2 * BKx * BSTR_S) * 4)

__global__ void __launch_bounds__(128)
single_gemm(const float* __restrict__ A, int lda, size_t strideA,
            const int* __restrict__ cnt, int mfull, int mtiles,
            const float* __restrict__ Bg, int ldb, size_t strideB,
            float* __restrict__ Out, int ldo, size_t strideOut, int K) {
    extern __shared__ float sm[];
    float* As = sm;                      // 2 * 128 * 36
    float* Bs = sm + 2 * BM * ASTR;      // 2 * 32 * 136

    int e = blockIdx.x / mtiles;
    int mt = blockIdx.x - e * mtiles;
    int noff = blockIdx.y * 128;
    int nrows = cnt ? (cnt[e] - mt * BM) : (mfull - mt * BM);
    if (nrows <= 0) return;
    int valid = min(BM, nrows);

    int tid = threadIdx.x;
    int acol = (tid & 7) * 4;
    int arow0 = tid >> 3;
    const float* aptr[8];
    #pragma unroll
    for (int i = 0; i < 8; i++) {
        int r = arow0 + i * 16;
        int rr = min(r, valid - 1);
        aptr[i] = A + (size_t)e * strideA + ((size_t)mt * BM + rr) * lda + acol;
    }
    const float* bptr[8];
    {
        const float* B = Bg + (size_t)e * strideB + noff;
        #pragma unroll
        for (int i = 0; i < 8; i++) {
            int slot = tid + i * 128;
            int k = slot >> 5;
            int n4 = (slot & 31) * 4;
            bptr[i] = B + (size_t)k * ldb + n4;
        }
    }

    float c[4][8][4];
    #pragma unroll
    for (int a = 0; a < 4; a++)
        #pragma unroll
        for (int b = 0; b < 8; b++)
            #pragma unroll
            for (int r = 0; r < 4; r++) c[a][b][r] = 0.f;

    int warp = tid >> 5, lane = tid & 31;
    int wm = warp & 1, wn = warp >> 1;
    int g = lane >> 2, t4 = lane & 3;

    auto issue = [&](int s) {
        float* as = As + s * BM * ASTR;
        #pragma unroll
        for (int i = 0; i < 8; i++) {
            int r = arow0 + i * 16;
            cp16(as + r * ASTR + acol, aptr[i]);
            aptr[i] += BKx;
        }
        float* bs = Bs + s * BKx * BSTR_S;
        #pragma unroll
        for (int i = 0; i < 8; i++) {
            int slot = tid + i * 128;
            int k = slot >> 5;
            int n4 = (slot & 31) * 4;
            cp16(bs + k * BSTR_S + n4, bptr[i]);
            bptr[i] += (size_t)BKx * ldb;
        }
    };

    issue(0); cp_commit();
    int nk = K / BKx;
    for (int kb = 0; kb < nk; kb++) {
        int s = kb & 1;
        if (kb + 1 < nk) issue(s ^ 1);
        cp_commit();
        cp_wait1();
        __syncthreads();
        const float* as = As + s * BM * ASTR;
        const float* bs = Bs + s * BKx * BSTR_S;
        #pragma unroll
        for (int kk = 0; kk < 4; kk++) {
            unsigned af[4][4];
            int kc = kk * 8 + t4;
            #pragma unroll
            for (int mf = 0; mf < 4; mf++) {
                int r0 = wm * 64 + mf * 16 + g;
                af[mf][0] = tf32r(as[r0 * ASTR + kc]);
                af[mf][1] = tf32r(as[(r0 + 8) * ASTR + kc]);
                af[mf][2] = tf32r(as[r0 * ASTR + kc + 4]);
                af[mf][3] = tf32r(as[(r0 + 8) * ASTR + kc + 4]);
            }
            unsigned bf[8][2];
            #pragma unroll
            for (int nf = 0; nf < 8; nf++) {
                int nn = wn * 64 + nf * 8 + g;
                bf[nf][0] = tf32r(bs[kc * BSTR_S + nn]);
                bf[nf][1] = tf32r(bs[(kc + 4) * BSTR_S + nn]);
            }
            #pragma unroll
            for (int mf = 0; mf < 4; mf++)
                #pragma unroll
                for (int nf = 0; nf < 8; nf++)
                    mma8(c[mf][nf], af[mf][0], af[mf][1], af[mf][2], af[mf][3], bf[nf][0], bf[nf][1]);
        }
        __syncthreads();
    }

    float* outp = Out + (size_t)e * strideOut + (size_t)mt * BM * ldo + noff;
    #pragma unroll
    for (int mf = 0; mf < 4; mf++)
        #pragma unroll
        for (int nf = 0; nf < 8; nf++) {
            int r0 = wm * 64 + mf * 16 + g;
            int cc = wn * 64 + nf * 8 + t4 * 2;
            #pragma unroll
            for (int h = 0; h < 2; h++) {
                int r = r0 + h * 8;
                if (r < valid)
                    *(float2*)(outp + (size_t)r * ldo + cc) =
                        make_float2(c[mf][nf][h * 2 + 0], c[mf][nf][h * 2 + 1]);
            }
        }
}

// ---------------- combine: routed + sigmoid-gated shared ----------------
__global__ void combine_kernel(float* __restrict__ out) {
    int t = blockIdx.x;
    __shared__ int rows[TOPK];
    __shared__ float ws[TOPK];
    if (threadIdx.x < TOPK) {
        int k = threadIdx.x;
        int ee = d_topk_idx[t * TOPK + k];
        int p  = d_pos[t * TOPK + k];
        rows[k] = (p < CAP) ? (ee * CAP + p) : -1;
        ws[k] = d_topk_w[t * TOPK + k];
    }
    __syncthreads();
    float sg = 1.f / (1.f + expf(-d_sgate[t]));
    #pragma unroll
    for (int j = 0; j < 2; j++) {
        int h = threadIdx.x * 4 + j * 1024;
        float4 acc = *(const float4*)(d_s2 + (size_t)t * H_DIM + h);
        acc.x *= sg; acc.y *= sg; acc.z *= sg; acc.w *= sg;
        #pragma unroll
        for (int k = 0; k < TOPK; k++) {
            int r = rows[k];
            if (r >= 0) {
                float w = ws[k];
                float4 y = *(const float4*)(d_yb + (size_t)r * H_DIM + h);
                acc.x += w * y.x; acc.y += w * y.y; acc.z += w * y.z; acc.w += w * y.w;
            }
        }
        *(float4*)(out + (size_t)t * H_DIM + h) = acc;
    }
}

// ---------------- launch ----------------
extern "C" void kernel_launch(void* const* d_in, const int* in_sizes, int n_in,
                              void* d_out, int out_size) {
    (void)in_sizes; (void)n_in; (void)out_size;
    const float* x   = (const float*)d_in[0];
    const float* gw  = (const float*)d_in[1];
    const float* w1  = (const float*)d_in[2];
    const float* w3  = (const float*)d_in[3];
    const float* w2  = (const float*)d_in[4];
    const float* ws1 = (const float*)d_in[5];
    const float* ws3 = (const float*)d_in[6];
    const float* ws2 = (const float*)d_in[7];
    const float* wsg = (const float*)d_in[8];
    float* out = (float*)d_out;

    cudaFuncSetAttribute(dual_gemm_silu, cudaFuncAttributeMaxDynamicSharedMemorySize, SMEM_DUAL);
    cudaFuncSetAttribute(single_gemm,    cudaFuncAttributeMaxDynamicSharedMemorySize, SMEM_SINGLE);

    float *gbuf, *yb, *s1, *s2;
    int *cnt, *toklist;
    cudaGetSymbolAddress((void**)&gbuf, d_gbuf);
    cudaGetSymbolAddress((void**)&yb, d_yb);
    cudaGetSymbolAddress((void**)&s1, d_s1);
    cudaGetSymbolAddress((void**)&s2, d_s2);
    cudaGetSymbolAddress((void**)&cnt, d_cnt);
    cudaGetSymbolAddress((void**)&toklist, d_toklist);

    router_kernel<<<T_TOK, 256>>>(x, gw, wsg);
    dispatch_kernel<<<E_NUM, 256>>>();

    // experts: G = silu(X@w1) * (X@w3)   [gathered rows]
    dual_gemm_silu<<<dim3(E_NUM * 2, I_DIM / 64), 128, SMEM_DUAL>>>(
        x, H_DIM, 0, toklist, cnt, 0, 2,
        w1, w3, I_DIM, (size_t)H_DIM * I_DIM,
        gbuf, I_DIM, (size_t)CAP * I_DIM, H_DIM);

    // shared: S1 = silu(X@ws1) * (X@ws3)
    dual_gemm_silu<<<dim3(8, IS_DIM / 64), 128, SMEM_DUAL>>>(
        x, H_DIM, 0, nullptr, nullptr, T_TOK, 8,
        ws1, ws3, IS_DIM, 0,
        s1, IS_DIM, 0, H_DIM);

    // experts: Y = G @ w2
    single_gemm<<<dim3(E_NUM * 2, H_DIM / 128), 128, SMEM_SINGLE>>>(
        gbuf, I_DIM, (size_t)CAP * I_DIM, cnt, 0, 2,
        w2, H_DIM, (size_t)I_DIM * H_DIM,
        yb, H_DIM, (size_t)CAP * H_DIM, I_DIM);

    // shared: S2 = S1 @ ws2
    single_gemm<<<dim3(8, H_DIM / 128), 128, SMEM_SINGLE>>>(
        s1, IS_DIM, 0, nullptr, T_TOK, 8,
        ws2, H_DIM, 0,
        s2, H_DIM, 0, IS_DIM);

    combine_kernel<<<T_TOK, 256>>>(out);
}